// round 1
// baseline (speedup 1.0000x reference)
#include <cuda_runtime.h>
#include <math.h>

// Problem dims (fixed by the dataset)
#define B_   2
#define S_   2048
#define D_   1024
#define H_   16
#define DK_  64
#define MTOT (B_ * S_)   // 4096 rows for all projections

// ---------------------------------------------------------------------------
// Scratch (device globals: allocation-free per harness rules)
// ---------------------------------------------------------------------------
__device__ float g_q[B_ * H_ * S_ * DK_];
__device__ float g_k[B_ * H_ * S_ * DK_];
__device__ float g_v[B_ * H_ * S_ * DK_];
__device__ float g_att[B_ * H_ * S_ * DK_];  // [b][h][s][d] contiguous; its flat
                                             // view IS the reference's buggy
                                             // reshape -> feeds output GEMM

// ---------------------------------------------------------------------------
// SGEMM: C[M=4096, N=1024] = A[4096,1024] @ W[1024,1024] + bias
// 128x128 block tile, BK=8, 256 threads, 8x8 per-thread register tile.
// head_layout=1: write C[r, c] to g-style [b][h][s][d] layout.
// ---------------------------------------------------------------------------
#define BM 128
#define BN 128
#define BKG 8

__global__ __launch_bounds__(256)
void sgemm_kernel(const float* __restrict__ A, const float* __restrict__ W,
                  const float* __restrict__ bias, float* __restrict__ C,
                  int head_layout) {
    __shared__ float As[BKG][BM];
    __shared__ float Bs[BKG][BN];

    const int tid   = threadIdx.x;
    const int crow0 = blockIdx.y * BM;
    const int ccol0 = blockIdx.x * BN;

    const int ty = tid / 16;      // 0..15
    const int tx = tid % 16;      // 0..15

    // A tile load mapping: 128 rows x 8 cols = 1024 floats = 256 thr * float4
    const int a_row = tid >> 1;          // 0..127
    const int a_col = (tid & 1) * 4;     // 0 or 4
    // W tile load mapping: 8 rows x 128 cols
    const int b_row = tid >> 5;          // 0..7
    const int b_col = (tid & 31) * 4;    // 0..124

    float acc[8][8];
#pragma unroll
    for (int i = 0; i < 8; i++)
#pragma unroll
        for (int j = 0; j < 8; j++) acc[i][j] = 0.0f;

    for (int kt = 0; kt < D_; kt += BKG) {
        float4 av = *(const float4*)&A[(size_t)(crow0 + a_row) * D_ + kt + a_col];
        As[a_col + 0][a_row] = av.x;
        As[a_col + 1][a_row] = av.y;
        As[a_col + 2][a_row] = av.z;
        As[a_col + 3][a_row] = av.w;
        float4 wv = *(const float4*)&W[(size_t)(kt + b_row) * D_ + ccol0 + b_col];
        *(float4*)&Bs[b_row][b_col] = wv;
        __syncthreads();

#pragma unroll
        for (int k = 0; k < BKG; k++) {
            float ra[8], rb[8];
            *(float4*)&ra[0] = *(const float4*)&As[k][ty * 8];
            *(float4*)&ra[4] = *(const float4*)&As[k][ty * 8 + 4];
            *(float4*)&rb[0] = *(const float4*)&Bs[k][tx * 8];
            *(float4*)&rb[4] = *(const float4*)&Bs[k][tx * 8 + 4];
#pragma unroll
            for (int i = 0; i < 8; i++)
#pragma unroll
                for (int j = 0; j < 8; j++)
                    acc[i][j] += ra[i] * rb[j];
        }
        __syncthreads();
    }

    // Epilogue
#pragma unroll
    for (int i = 0; i < 8; i++) {
        const int r = crow0 + ty * 8 + i;
#pragma unroll
        for (int j = 0; j < 8; j++) {
            const int c = ccol0 + tx * 8 + j;
            const float v = acc[i][j] + bias[c];
            if (head_layout) {
                const int b = r / S_, s = r % S_;
                const int h = c / DK_, d = c % DK_;
                C[(((size_t)(b * H_ + h)) * S_ + s) * DK_ + d] = v;
            } else {
                C[(size_t)r * D_ + c] = v;
            }
        }
    }
}

// ---------------------------------------------------------------------------
// Flash attention (causal), fp32.
// CTA: 64 query rows for one (b, h); key blocks of 32.
// 128 threads: ty = tid/8 -> 4 q-rows, tx = tid%8 -> 4 k-cols (S) / 8 d-cols (O)
// ---------------------------------------------------------------------------
#define BQ    64
#define BKA   32
#define QPAD  68   // 64 + 4 pad, keeps float4 alignment
#define PPAD  36

__global__ __launch_bounds__(128)
void attn_kernel() {
    __shared__ float Qs[BQ][QPAD];     // 17408 B
    __shared__ float Ks[BKA][QPAD];    //  8704 B
    __shared__ float Vs[BKA][QPAD];    //  8704 B
    __shared__ float Ps[BQ][PPAD];     //  9216 B  (total 44032 < 48K)

    const int tid = threadIdx.x;
    const int qi  = blockIdx.x;        // 0..31
    const int h   = blockIdx.y;
    const int b   = blockIdx.z;
    const int bh  = b * H_ + h;
    const size_t base = (size_t)bh * S_ * DK_;
    const float* Q  = g_q  + base;
    const float* Kp = g_k  + base;
    const float* Vp = g_v  + base;
    float*       Op = g_att + base;

    const int q0 = qi * BQ;
    const int ty = tid / 8;    // 0..15
    const int tx = tid % 8;    // 0..7

    // Load Q tile (64x64): 1024 float4 / 128 threads = 8 each
#pragma unroll
    for (int i = 0; i < 8; i++) {
        const int idx = tid + i * 128;
        const int r  = idx >> 4;
        const int c4 = (idx & 15) * 4;
        *(float4*)&Qs[r][c4] = *(const float4*)&Q[(size_t)(q0 + r) * DK_ + c4];
    }

    float m_i[4], l_i[4], o_acc[4][8];
#pragma unroll
    for (int i = 0; i < 4; i++) {
        m_i[i] = -1e30f;
        l_i[i] = 0.0f;
#pragma unroll
        for (int j = 0; j < 8; j++) o_acc[i][j] = 0.0f;
    }

    const float scale = 0.125f;  // 1/sqrt(64)
    const int nkb = (q0 + BQ) / BKA;  // causal: keys up to q0+63

    for (int kb = 0; kb < nkb; kb++) {
        __syncthreads();  // protect Ks/Vs/Ps from prior-iteration readers
        const int k0 = kb * BKA;

        // Load K, V tiles (32x64 each): 512 float4 / 128 threads = 4 each
#pragma unroll
        for (int i = 0; i < 4; i++) {
            const int idx = tid + i * 128;
            const int r  = idx >> 4;
            const int c4 = (idx & 15) * 4;
            *(float4*)&Ks[r][c4] = *(const float4*)&Kp[(size_t)(k0 + r) * DK_ + c4];
            *(float4*)&Vs[r][c4] = *(const float4*)&Vp[(size_t)(k0 + r) * DK_ + c4];
        }
        __syncthreads();

        // S = Q @ K^T  (per-thread 4x4)
        float s_reg[4][4];
#pragma unroll
        for (int i = 0; i < 4; i++)
#pragma unroll
            for (int j = 0; j < 4; j++) s_reg[i][j] = 0.0f;

#pragma unroll
        for (int kk = 0; kk < DK_; kk += 4) {
            float4 qv[4], kv[4];
#pragma unroll
            for (int i = 0; i < 4; i++) qv[i] = *(const float4*)&Qs[ty * 4 + i][kk];
#pragma unroll
            for (int j = 0; j < 4; j++) kv[j] = *(const float4*)&Ks[tx * 4 + j][kk];
#pragma unroll
            for (int i = 0; i < 4; i++)
#pragma unroll
                for (int j = 0; j < 4; j++)
                    s_reg[i][j] += qv[i].x * kv[j].x + qv[i].y * kv[j].y +
                                   qv[i].z * kv[j].z + qv[i].w * kv[j].w;
        }

        // Scale, causal mask, online softmax (row groups: 8 tx lanes share row)
#pragma unroll
        for (int i = 0; i < 4; i++) {
            const int qg = q0 + ty * 4 + i;
            float mx = -1e30f;
#pragma unroll
            for (int j = 0; j < 4; j++) {
                const int kg = k0 + tx * 4 + j;
                float sv = s_reg[i][j] * scale;
                if (kg > qg) sv = -1e30f;
                s_reg[i][j] = sv;
                mx = fmaxf(mx, sv);
            }
            mx = fmaxf(mx, __shfl_xor_sync(0xffffffffu, mx, 1));
            mx = fmaxf(mx, __shfl_xor_sync(0xffffffffu, mx, 2));
            mx = fmaxf(mx, __shfl_xor_sync(0xffffffffu, mx, 4));

            const float mnew = fmaxf(m_i[i], mx);
            const float corr = __expf(m_i[i] - mnew);
            m_i[i] = mnew;

            float ssum = 0.0f;
#pragma unroll
            for (int j = 0; j < 4; j++) {
                const float p = __expf(s_reg[i][j] - mnew);
                s_reg[i][j] = p;
                ssum += p;
            }
            ssum += __shfl_xor_sync(0xffffffffu, ssum, 1);
            ssum += __shfl_xor_sync(0xffffffffu, ssum, 2);
            ssum += __shfl_xor_sync(0xffffffffu, ssum, 4);
            l_i[i] = l_i[i] * corr + ssum;

#pragma unroll
            for (int j = 0; j < 8; j++) o_acc[i][j] *= corr;

            *(float4*)&Ps[ty * 4 + i][tx * 4] =
                make_float4(s_reg[i][0], s_reg[i][1], s_reg[i][2], s_reg[i][3]);
        }
        __syncthreads();

        // O += P @ V
#pragma unroll
        for (int kk = 0; kk < BKA; kk += 4) {
            float4 pv[4];
#pragma unroll
            for (int i = 0; i < 4; i++) pv[i] = *(const float4*)&Ps[ty * 4 + i][kk];
#pragma unroll
            for (int k2 = 0; k2 < 4; k2++) {
                const float4 v0 = *(const float4*)&Vs[kk + k2][tx * 8];
                const float4 v1 = *(const float4*)&Vs[kk + k2][tx * 8 + 4];
#pragma unroll
                for (int i = 0; i < 4; i++) {
                    const float pk = (k2 == 0) ? pv[i].x :
                                     (k2 == 1) ? pv[i].y :
                                     (k2 == 2) ? pv[i].z : pv[i].w;
                    o_acc[i][0] += pk * v0.x;
                    o_acc[i][1] += pk * v0.y;
                    o_acc[i][2] += pk * v0.z;
                    o_acc[i][3] += pk * v0.w;
                    o_acc[i][4] += pk * v1.x;
                    o_acc[i][5] += pk * v1.y;
                    o_acc[i][6] += pk * v1.z;
                    o_acc[i][7] += pk * v1.w;
                }
            }
        }
    }

    // Epilogue: normalize, write attention output in [b][h][s][d] layout
#pragma unroll
    for (int i = 0; i < 4; i++) {
        const float inv = 1.0f / l_i[i];
        const int qg = q0 + ty * 4 + i;
#pragma unroll
        for (int j = 0; j < 8; j++)
            Op[(size_t)qg * DK_ + tx * 8 + j] = o_acc[i][j] * inv;
    }
}

// ---------------------------------------------------------------------------
// Launch
// ---------------------------------------------------------------------------
extern "C" void kernel_launch(void* const* d_in, const int* in_sizes, int n_in,
                              void* d_out, int out_size) {
    (void)in_sizes; (void)n_in; (void)out_size;
    const float* query = (const float*)d_in[0];
    const float* key   = (const float*)d_in[1];
    const float* value = (const float*)d_in[2];
    // d_in[3] = mask: fixed causal triu(k=1) — applied analytically in-kernel
    const float* Wq = (const float*)d_in[4];
    const float* bq = (const float*)d_in[5];
    const float* Wk = (const float*)d_in[6];
    const float* bk = (const float*)d_in[7];
    const float* Wv = (const float*)d_in[8];
    const float* bv = (const float*)d_in[9];
    const float* Wo = (const float*)d_in[10];
    const float* bo = (const float*)d_in[11];
    float* out = (float*)d_out;

    float *qp, *kp, *vp, *attp;
    cudaGetSymbolAddress((void**)&qp,  g_q);
    cudaGetSymbolAddress((void**)&kp,  g_k);
    cudaGetSymbolAddress((void**)&vp,  g_v);
    cudaGetSymbolAddress((void**)&attp, g_att);

    dim3 gg(D_ / BN, MTOT / BM);  // (8, 32)
    sgemm_kernel<<<gg, 256>>>(query, Wq, bq, qp, 1);
    sgemm_kernel<<<gg, 256>>>(key,   Wk, bk, kp, 1);
    sgemm_kernel<<<gg, 256>>>(value, Wv, bv, vp, 1);

    attn_kernel<<<dim3(S_ / BQ, H_, B_), 128>>>();

    sgemm_kernel<<<gg, 256>>>(attp, Wo, bo, out, 0);
}

// round 3
// speedup vs baseline: 1.3824x; 1.3824x over previous
#include <cuda_runtime.h>
#include <math.h>
#include <stdint.h>

// Problem dims (fixed by the dataset)
#define B_   2
#define S_   2048
#define D_   1024
#define H_   16
#define DK_  64
#define MTOT (B_ * S_)   // 4096 rows for all projections

// ---------------------------------------------------------------------------
// Scratch (device globals: allocation-free per harness rules)
// ---------------------------------------------------------------------------
__device__ float g_q[B_ * H_ * S_ * DK_];
__device__ float g_k[B_ * H_ * S_ * DK_];
__device__ float g_v[B_ * H_ * S_ * DK_];
__device__ float g_att[B_ * H_ * S_ * DK_];  // [b][h][s][d]; flat view IS the
                                             // reference's buggy reshape

// ---------------------------------------------------------------------------
// TF32 tensor-core GEMM:
//   C[M=4096, N=1024] = A[4096,1024] @ W[1024,1024] + bias
// CTA tile 128x128, BK=16, 256 threads (8 warps), warp tile 32x64.
// mma.sync.aligned.m16n8k8.row.col.f32.tf32.tf32.f32
// head_layout=1: write C[r,c] into [b][h][s][d] layout.
// ---------------------------------------------------------------------------
#define GBM 128
#define GBN 128
#define GBK 16
#define APAD 132   // smem row stride (floats) to spread banks

__device__ __forceinline__ uint32_t f2tf32(float x) {
    uint32_t r;
    asm("cvt.rna.tf32.f32 %0, %1;" : "=r"(r) : "f"(x));
    return r;
}

__device__ __forceinline__ void mma_tf32(float* d, const uint32_t* a, const uint32_t* b) {
    asm volatile(
        "mma.sync.aligned.m16n8k8.row.col.f32.tf32.tf32.f32 "
        "{%0,%1,%2,%3}, {%4,%5,%6,%7}, {%8,%9}, {%0,%1,%2,%3};"
        : "+f"(d[0]), "+f"(d[1]), "+f"(d[2]), "+f"(d[3])
        : "r"(a[0]), "r"(a[1]), "r"(a[2]), "r"(a[3]), "r"(b[0]), "r"(b[1]));
}

__global__ __launch_bounds__(256)
void gemm_tf32(const float* __restrict__ A, const float* __restrict__ W,
               const float* __restrict__ bias, float* __restrict__ C,
               int head_layout) {
    __shared__ uint32_t As[GBK][APAD];  // [k][m]
    __shared__ uint32_t Bs[GBK][APAD];  // [k][n]

    const int tid   = threadIdx.x;
    const int wid   = tid >> 5;
    const int lane  = tid & 31;
    const int g     = lane >> 2;   // groupID 0..7
    const int tig   = lane & 3;    // thread-in-group 0..3

    const int warp_m = wid & 3;    // 0..3 -> 32-row slab
    const int warp_n = wid >> 2;   // 0..1 -> 64-col slab

    const int row0 = blockIdx.y * GBM;
    const int col0 = blockIdx.x * GBN;

    // A tile load: 128x16 floats = 512 float4; idx -> (row=idx>>2, c4=(idx&3)*4)
    // W tile load: 16x128 floats = 512 float4; idx -> (krow=idx>>5, c4=(idx&31)*4)
    float acc[2][8][4];
#pragma unroll
    for (int mt = 0; mt < 2; mt++)
#pragma unroll
        for (int nt = 0; nt < 8; nt++)
#pragma unroll
            for (int i = 0; i < 4; i++) acc[mt][nt][i] = 0.0f;

    for (int kt = 0; kt < D_; kt += GBK) {
        // --- load A tile ---
#pragma unroll
        for (int h = 0; h < 2; h++) {
            const int idx = tid + h * 256;
            const int r   = idx >> 2;
            const int c4  = (idx & 3) * 4;
            float4 av = *(const float4*)&A[(size_t)(row0 + r) * D_ + kt + c4];
            As[c4 + 0][r] = f2tf32(av.x);
            As[c4 + 1][r] = f2tf32(av.y);
            As[c4 + 2][r] = f2tf32(av.z);
            As[c4 + 3][r] = f2tf32(av.w);
        }
        // --- load W tile ---
#pragma unroll
        for (int h = 0; h < 2; h++) {
            const int idx = tid + h * 256;
            const int kr  = idx >> 5;
            const int c4  = (idx & 31) * 4;
            float4 wv = *(const float4*)&W[(size_t)(kt + kr) * D_ + col0 + c4];
            uint4 u;
            u.x = f2tf32(wv.x);
            u.y = f2tf32(wv.y);
            u.z = f2tf32(wv.z);
            u.w = f2tf32(wv.w);
            *(uint4*)&Bs[kr][c4] = u;
        }
        __syncthreads();

#pragma unroll
        for (int ks = 0; ks < GBK; ks += 8) {
            uint32_t afr[2][4], bfr[8][2];
#pragma unroll
            for (int mt = 0; mt < 2; mt++) {
                const int r0 = warp_m * 32 + mt * 16;
                afr[mt][0] = As[ks + tig    ][r0 + g    ];
                afr[mt][1] = As[ks + tig    ][r0 + g + 8];
                afr[mt][2] = As[ks + tig + 4][r0 + g    ];
                afr[mt][3] = As[ks + tig + 4][r0 + g + 8];
            }
#pragma unroll
            for (int nt = 0; nt < 8; nt++) {
                const int n0 = warp_n * 64 + nt * 8;
                bfr[nt][0] = Bs[ks + tig    ][n0 + g];
                bfr[nt][1] = Bs[ks + tig + 4][n0 + g];
            }
#pragma unroll
            for (int mt = 0; mt < 2; mt++)
#pragma unroll
                for (int nt = 0; nt < 8; nt++)
                    mma_tf32(acc[mt][nt], afr[mt], bfr[nt]);
        }
        __syncthreads();
    }

    // Epilogue: fragment (c0,c1)=(row=g, col=tig*2, tig*2+1); (c2,c3)=row g+8
#pragma unroll
    for (int mt = 0; mt < 2; mt++) {
#pragma unroll
        for (int nt = 0; nt < 8; nt++) {
            const int cbase = col0 + warp_n * 64 + nt * 8 + tig * 2;
#pragma unroll
            for (int half = 0; half < 2; half++) {
                const int r = row0 + warp_m * 32 + mt * 16 + g + half * 8;
#pragma unroll
                for (int cc = 0; cc < 2; cc++) {
                    const int c = cbase + cc;
                    const float v = acc[mt][nt][half * 2 + cc] + bias[c];
                    if (head_layout) {
                        const int b = r / S_, s = r % S_;
                        const int hh = c / DK_, d = c % DK_;
                        C[(((size_t)(b * H_ + hh)) * S_ + s) * DK_ + d] = v;
                    } else {
                        C[(size_t)r * D_ + c] = v;
                    }
                }
            }
        }
    }
}

// ---------------------------------------------------------------------------
// Flash attention (causal), fp32 — unchanged from R1.
// ---------------------------------------------------------------------------
#define BQ    64
#define BKA   32
#define QPAD  68
#define PPAD  36

__global__ __launch_bounds__(128)
void attn_kernel() {
    __shared__ float Qs[BQ][QPAD];
    __shared__ float Ks[BKA][QPAD];
    __shared__ float Vs[BKA][QPAD];
    __shared__ float Ps[BQ][PPAD];

    const int tid = threadIdx.x;
    const int qi  = blockIdx.x;
    const int h   = blockIdx.y;
    const int b   = blockIdx.z;
    const int bh  = b * H_ + h;
    const size_t base = (size_t)bh * S_ * DK_;
    const float* Q  = g_q  + base;
    const float* Kp = g_k  + base;
    const float* Vp = g_v  + base;
    float*       Op = g_att + base;

    const int q0 = qi * BQ;
    const int ty = tid / 8;
    const int tx = tid % 8;

#pragma unroll
    for (int i = 0; i < 8; i++) {
        const int idx = tid + i * 128;
        const int r  = idx >> 4;
        const int c4 = (idx & 15) * 4;
        *(float4*)&Qs[r][c4] = *(const float4*)&Q[(size_t)(q0 + r) * DK_ + c4];
    }

    float m_i[4], l_i[4], o_acc[4][8];
#pragma unroll
    for (int i = 0; i < 4; i++) {
        m_i[i] = -1e30f;
        l_i[i] = 0.0f;
#pragma unroll
        for (int j = 0; j < 8; j++) o_acc[i][j] = 0.0f;
    }

    const float scale = 0.125f;
    const int nkb = (q0 + BQ) / BKA;

    for (int kb = 0; kb < nkb; kb++) {
        __syncthreads();
        const int k0 = kb * BKA;

#pragma unroll
        for (int i = 0; i < 4; i++) {
            const int idx = tid + i * 128;
            const int r  = idx >> 4;
            const int c4 = (idx & 15) * 4;
            *(float4*)&Ks[r][c4] = *(const float4*)&Kp[(size_t)(k0 + r) * DK_ + c4];
            *(float4*)&Vs[r][c4] = *(const float4*)&Vp[(size_t)(k0 + r) * DK_ + c4];
        }
        __syncthreads();

        float s_reg[4][4];
#pragma unroll
        for (int i = 0; i < 4; i++)
#pragma unroll
            for (int j = 0; j < 4; j++) s_reg[i][j] = 0.0f;

#pragma unroll
        for (int kk = 0; kk < DK_; kk += 4) {
            float4 qv[4], kv[4];
#pragma unroll
            for (int i = 0; i < 4; i++) qv[i] = *(const float4*)&Qs[ty * 4 + i][kk];
#pragma unroll
            for (int j = 0; j < 4; j++) kv[j] = *(const float4*)&Ks[tx * 4 + j][kk];
#pragma unroll
            for (int i = 0; i < 4; i++)
#pragma unroll
                for (int j = 0; j < 4; j++)
                    s_reg[i][j] += qv[i].x * kv[j].x + qv[i].y * kv[j].y +
                                   qv[i].z * kv[j].z + qv[i].w * kv[j].w;
        }

#pragma unroll
        for (int i = 0; i < 4; i++) {
            const int qg = q0 + ty * 4 + i;
            float mx = -1e30f;
#pragma unroll
            for (int j = 0; j < 4; j++) {
                const int kg = k0 + tx * 4 + j;
                float sv = s_reg[i][j] * scale;
                if (kg > qg) sv = -1e30f;
                s_reg[i][j] = sv;
                mx = fmaxf(mx, sv);
            }
            mx = fmaxf(mx, __shfl_xor_sync(0xffffffffu, mx, 1));
            mx = fmaxf(mx, __shfl_xor_sync(0xffffffffu, mx, 2));
            mx = fmaxf(mx, __shfl_xor_sync(0xffffffffu, mx, 4));

            const float mnew = fmaxf(m_i[i], mx);
            const float corr = __expf(m_i[i] - mnew);
            m_i[i] = mnew;

            float ssum = 0.0f;
#pragma unroll
            for (int j = 0; j < 4; j++) {
                const float p = __expf(s_reg[i][j] - mnew);
                s_reg[i][j] = p;
                ssum += p;
            }
            ssum += __shfl_xor_sync(0xffffffffu, ssum, 1);
            ssum += __shfl_xor_sync(0xffffffffu, ssum, 2);
            ssum += __shfl_xor_sync(0xffffffffu, ssum, 4);
            l_i[i] = l_i[i] * corr + ssum;

#pragma unroll
            for (int j = 0; j < 8; j++) o_acc[i][j] *= corr;

            *(float4*)&Ps[ty * 4 + i][tx * 4] =
                make_float4(s_reg[i][0], s_reg[i][1], s_reg[i][2], s_reg[i][3]);
        }
        __syncthreads();

#pragma unroll
        for (int kk = 0; kk < BKA; kk += 4) {
            float4 pv[4];
#pragma unroll
            for (int i = 0; i < 4; i++) pv[i] = *(const float4*)&Ps[ty * 4 + i][kk];
#pragma unroll
            for (int k2 = 0; k2 < 4; k2++) {
                const float4 v0 = *(const float4*)&Vs[kk + k2][tx * 8];
                const float4 v1 = *(const float4*)&Vs[kk + k2][tx * 8 + 4];
#pragma unroll
                for (int i = 0; i < 4; i++) {
                    const float pk = (k2 == 0) ? pv[i].x :
                                     (k2 == 1) ? pv[i].y :
                                     (k2 == 2) ? pv[i].z : pv[i].w;
                    o_acc[i][0] += pk * v0.x;
                    o_acc[i][1] += pk * v0.y;
                    o_acc[i][2] += pk * v0.z;
                    o_acc[i][3] += pk * v0.w;
                    o_acc[i][4] += pk * v1.x;
                    o_acc[i][5] += pk * v1.y;
                    o_acc[i][6] += pk * v1.z;
                    o_acc[i][7] += pk * v1.w;
                }
            }
        }
    }

#pragma unroll
    for (int i = 0; i < 4; i++) {
        const float inv = 1.0f / l_i[i];
        const int qg = q0 + ty * 4 + i;
#pragma unroll
        for (int j = 0; j < 8; j++)
            Op[(size_t)qg * DK_ + tx * 8 + j] = o_acc[i][j] * inv;
    }
}

// ---------------------------------------------------------------------------
// Launch
// ---------------------------------------------------------------------------
extern "C" void kernel_launch(void* const* d_in, const int* in_sizes, int n_in,
                              void* d_out, int out_size) {
    (void)in_sizes; (void)n_in; (void)out_size;
    const float* query = (const float*)d_in[0];
    const float* key   = (const float*)d_in[1];
    const float* value = (const float*)d_in[2];
    // d_in[3] = mask: fixed causal triu(k=1) — applied analytically in-kernel
    const float* Wq = (const float*)d_in[4];
    const float* bq = (const float*)d_in[5];
    const float* Wk = (const float*)d_in[6];
    const float* bk = (const float*)d_in[7];
    const float* Wv = (const float*)d_in[8];
    const float* bv = (const float*)d_in[9];
    const float* Wo = (const float*)d_in[10];
    const float* bo = (const float*)d_in[11];
    float* out = (float*)d_out;

    float *qp, *kp, *vp, *attp;
    cudaGetSymbolAddress((void**)&qp,  g_q);
    cudaGetSymbolAddress((void**)&kp,  g_k);
    cudaGetSymbolAddress((void**)&vp,  g_v);
    cudaGetSymbolAddress((void**)&attp, g_att);

    dim3 gg(D_ / GBN, MTOT / GBM);  // (8, 32)
    gemm_tf32<<<gg, 256>>>(query, Wq, bq, qp, 1);
    gemm_tf32<<<gg, 256>>>(key,   Wk, bk, kp, 1);
    gemm_tf32<<<gg, 256>>>(value, Wv, bv, vp, 1);

    attn_kernel<<<dim3(S_ / BQ, H_, B_), 128>>>();

    gemm_tf32<<<gg, 256>>>(attp, Wo, bo, out, 0);
}

// round 5
// speedup vs baseline: 1.9702x; 1.4252x over previous
#include <cuda_runtime.h>
#include <math.h>
#include <stdint.h>

// Problem dims (fixed by the dataset)
#define B_   2
#define S_   2048
#define D_   1024
#define H_   16
#define DK_  64
#define MTOT (B_ * S_)

// ---------------------------------------------------------------------------
// Scratch
// ---------------------------------------------------------------------------
__device__ float g_q[B_ * H_ * S_ * DK_];
__device__ float g_k[B_ * H_ * S_ * DK_];
__device__ float g_v[B_ * H_ * S_ * DK_];
__device__ float g_att[B_ * H_ * S_ * DK_];

__device__ __forceinline__ uint32_t f2tf32(float x) {
    uint32_t r;
    asm("cvt.rna.tf32.f32 %0, %1;" : "=r"(r) : "f"(x));
    return r;
}

__device__ __forceinline__ void mma_tf32(float* d, const uint32_t* a, const uint32_t* b) {
    asm volatile(
        "mma.sync.aligned.m16n8k8.row.col.f32.tf32.tf32.f32 "
        "{%0,%1,%2,%3}, {%4,%5,%6,%7}, {%8,%9}, {%0,%1,%2,%3};"
        : "+f"(d[0]), "+f"(d[1]), "+f"(d[2]), "+f"(d[3])
        : "r"(a[0]), "r"(a[1]), "r"(a[2]), "r"(a[3]), "r"(b[0]), "r"(b[1]));
}

// ---------------------------------------------------------------------------
// TF32 tensor-core GEMM (unchanged from passing R3)
// ---------------------------------------------------------------------------
#define GBM 128
#define GBN 128
#define GBK 16
#define APAD 132

__global__ __launch_bounds__(256)
void gemm_tf32(const float* __restrict__ A, const float* __restrict__ W,
               const float* __restrict__ bias, float* __restrict__ C,
               int head_layout) {
    __shared__ uint32_t As[GBK][APAD];
    __shared__ uint32_t Bs[GBK][APAD];

    const int tid   = threadIdx.x;
    const int wid   = tid >> 5;
    const int lane  = tid & 31;
    const int g     = lane >> 2;
    const int tig   = lane & 3;

    const int warp_m = wid & 3;
    const int warp_n = wid >> 2;

    const int row0 = blockIdx.y * GBM;
    const int col0 = blockIdx.x * GBN;

    float acc[2][8][4];
#pragma unroll
    for (int mt = 0; mt < 2; mt++)
#pragma unroll
        for (int nt = 0; nt < 8; nt++)
#pragma unroll
            for (int i = 0; i < 4; i++) acc[mt][nt][i] = 0.0f;

    for (int kt = 0; kt < D_; kt += GBK) {
#pragma unroll
        for (int h = 0; h < 2; h++) {
            const int idx = tid + h * 256;
            const int r   = idx >> 2;
            const int c4  = (idx & 3) * 4;
            float4 av = *(const float4*)&A[(size_t)(row0 + r) * D_ + kt + c4];
            As[c4 + 0][r] = f2tf32(av.x);
            As[c4 + 1][r] = f2tf32(av.y);
            As[c4 + 2][r] = f2tf32(av.z);
            As[c4 + 3][r] = f2tf32(av.w);
        }
#pragma unroll
        for (int h = 0; h < 2; h++) {
            const int idx = tid + h * 256;
            const int kr  = idx >> 5;
            const int c4  = (idx & 31) * 4;
            float4 wv = *(const float4*)&W[(size_t)(kt + kr) * D_ + col0 + c4];
            uint4 u;
            u.x = f2tf32(wv.x);
            u.y = f2tf32(wv.y);
            u.z = f2tf32(wv.z);
            u.w = f2tf32(wv.w);
            *(uint4*)&Bs[kr][c4] = u;
        }
        __syncthreads();

#pragma unroll
        for (int ks = 0; ks < GBK; ks += 8) {
            uint32_t afr[2][4], bfr[8][2];
#pragma unroll
            for (int mt = 0; mt < 2; mt++) {
                const int r0 = warp_m * 32 + mt * 16;
                afr[mt][0] = As[ks + tig    ][r0 + g    ];
                afr[mt][1] = As[ks + tig    ][r0 + g + 8];
                afr[mt][2] = As[ks + tig + 4][r0 + g    ];
                afr[mt][3] = As[ks + tig + 4][r0 + g + 8];
            }
#pragma unroll
            for (int nt = 0; nt < 8; nt++) {
                const int n0 = warp_n * 64 + nt * 8;
                bfr[nt][0] = Bs[ks + tig    ][n0 + g];
                bfr[nt][1] = Bs[ks + tig + 4][n0 + g];
            }
#pragma unroll
            for (int mt = 0; mt < 2; mt++)
#pragma unroll
                for (int nt = 0; nt < 8; nt++)
                    mma_tf32(acc[mt][nt], afr[mt], bfr[nt]);
        }
        __syncthreads();
    }

#pragma unroll
    for (int mt = 0; mt < 2; mt++) {
#pragma unroll
        for (int nt = 0; nt < 8; nt++) {
            const int cbase = col0 + warp_n * 64 + nt * 8 + tig * 2;
#pragma unroll
            for (int half = 0; half < 2; half++) {
                const int r = row0 + warp_m * 32 + mt * 16 + g + half * 8;
#pragma unroll
                for (int cc = 0; cc < 2; cc++) {
                    const int c = cbase + cc;
                    const float v = acc[mt][nt][half * 2 + cc] + bias[c];
                    if (head_layout) {
                        const int b = r / S_, s = r % S_;
                        const int hh = c / DK_, d = c % DK_;
                        C[(((size_t)(b * H_ + hh)) * S_ + s) * DK_ + d] = v;
                    } else {
                        C[(size_t)r * D_ + c] = v;
                    }
                }
            }
        }
    }
}

// ---------------------------------------------------------------------------
// Tensor-core flash attention (causal), TF32 mma, fp32 softmax/accum.
// CTA: 64 q-rows for one (b,h); 4 warps x 16 rows. Key blocks of 32.
// Tile geometry (FIXED vs R4: strides now >= column count):
//   Ks[32 keys][68]  (64 dk cols + pad; 68%32=4  -> K-frag reads bank 4g+tig, CF)
//   Vs[32 keys][72]  (64 d  cols + pad; 72%32=8  -> V-frag reads bank 8tig+g, CF)
//   Ps[64 rows][36]  (32 key cols + pad; 36%32=4 -> A-frag reads bank 4g+tig, CF)
// Total smem: 8704 + 9216 + 9216 = 27136 B.
// ---------------------------------------------------------------------------
#define BQ   64
#define BKA  32
#define KST  68
#define VST  72
#define PST  36

__global__ __launch_bounds__(128)
void attn_tc() {
    __shared__ uint32_t Ks[BKA][KST];
    __shared__ uint32_t Vs[BKA][VST];
    __shared__ uint32_t Ps[BQ][PST];

    const int tid  = threadIdx.x;
    const int warp = tid >> 5;
    const int lane = tid & 31;
    const int g    = lane >> 2;   // 0..7
    const int tig  = lane & 3;    // 0..3

    const int qi = blockIdx.x;
    const int h  = blockIdx.y;
    const int b  = blockIdx.z;
    const size_t base = (size_t)(b * H_ + h) * S_ * DK_;
    const float* Kp = g_k + base;
    const float* Vp = g_v + base;

    const int q0   = qi * BQ;
    const int r_lo = q0 + warp * 16 + g;   // global q row for c0,c1
    const int r_hi = r_lo + 8;             // global q row for c2,c3

    // Q fragments in registers for all 8 k-chunks (DK=64)
    uint32_t qf[8][4];
    {
        const float* Qb = g_q + base + (size_t)(q0 + warp * 16) * DK_;
#pragma unroll
        for (int kc = 0; kc < 8; kc++) {
            qf[kc][0] = f2tf32(Qb[(size_t)g       * DK_ + kc * 8 + tig    ]);
            qf[kc][1] = f2tf32(Qb[(size_t)(g + 8) * DK_ + kc * 8 + tig    ]);
            qf[kc][2] = f2tf32(Qb[(size_t)g       * DK_ + kc * 8 + tig + 4]);
            qf[kc][3] = f2tf32(Qb[(size_t)(g + 8) * DK_ + kc * 8 + tig + 4]);
        }
    }

    float m_i[2] = {-1e30f, -1e30f};
    float l_i[2] = {0.0f, 0.0f};
    float o_acc[8][4];
#pragma unroll
    for (int nt = 0; nt < 8; nt++)
#pragma unroll
        for (int i = 0; i < 4; i++) o_acc[nt][i] = 0.0f;

    const float scale = 0.125f;
    const int nkb = (q0 + BQ) / BKA;   // causal: key blocks covering keys <= q0+63

    for (int kb = 0; kb < nkb; kb++) {
        const int k0 = kb * BKA;
        __syncthreads();  // protect Ks/Vs from previous-iteration readers

        // Load K,V tiles (32 rows x 64 cols each): 512 float4 / 128 thr = 4 each
#pragma unroll
        for (int i = 0; i < 4; i++) {
            const int idx = tid + i * 128;
            const int r   = idx >> 4;          // 0..31
            const int c4  = (idx & 15) * 4;    // 0..60
            float4 kv = *(const float4*)&Kp[(size_t)(k0 + r) * DK_ + c4];
            Ks[r][c4 + 0] = f2tf32(kv.x);
            Ks[r][c4 + 1] = f2tf32(kv.y);
            Ks[r][c4 + 2] = f2tf32(kv.z);
            Ks[r][c4 + 3] = f2tf32(kv.w);
            float4 vv = *(const float4*)&Vp[(size_t)(k0 + r) * DK_ + c4];
            Vs[r][c4 + 0] = f2tf32(vv.x);
            Vs[r][c4 + 1] = f2tf32(vv.y);
            Vs[r][c4 + 2] = f2tf32(vv.z);
            Vs[r][c4 + 3] = f2tf32(vv.w);
        }
        __syncthreads();

        // ---- S = Q @ K^T : 4 n-tiles (32 keys), 8 k-chunks (dk=64) ----
        float s[4][4];
#pragma unroll
        for (int nt = 0; nt < 4; nt++)
#pragma unroll
            for (int i = 0; i < 4; i++) s[nt][i] = 0.0f;

#pragma unroll
        for (int kc = 0; kc < 8; kc++) {
            uint32_t bf[4][2];
#pragma unroll
            for (int nt = 0; nt < 4; nt++) {
                bf[nt][0] = Ks[nt * 8 + g][kc * 8 + tig    ];
                bf[nt][1] = Ks[nt * 8 + g][kc * 8 + tig + 4];
            }
#pragma unroll
            for (int nt = 0; nt < 4; nt++)
                mma_tf32(s[nt], qf[kc], bf[nt]);
        }

        // ---- scale + causal mask + online softmax on fragments ----
#pragma unroll
        for (int half = 0; half < 2; half++) {
            const int qg = (half == 0) ? r_lo : r_hi;
            float mx = -1e30f;
#pragma unroll
            for (int nt = 0; nt < 4; nt++) {
#pragma unroll
                for (int cc = 0; cc < 2; cc++) {
                    const int kg = k0 + nt * 8 + tig * 2 + cc;
                    float sv = s[nt][half * 2 + cc] * scale;
                    if (kg > qg) sv = -1e30f;
                    s[nt][half * 2 + cc] = sv;
                    mx = fmaxf(mx, sv);
                }
            }
            mx = fmaxf(mx, __shfl_xor_sync(0xffffffffu, mx, 1));
            mx = fmaxf(mx, __shfl_xor_sync(0xffffffffu, mx, 2));

            const float mnew = fmaxf(m_i[half], mx);
            const float corr = __expf(m_i[half] - mnew);
            m_i[half] = mnew;

            float ssum = 0.0f;
#pragma unroll
            for (int nt = 0; nt < 4; nt++) {
#pragma unroll
                for (int cc = 0; cc < 2; cc++) {
                    const float p = __expf(s[nt][half * 2 + cc] - mnew);
                    s[nt][half * 2 + cc] = p;
                    ssum += p;
                }
            }
            ssum += __shfl_xor_sync(0xffffffffu, ssum, 1);
            ssum += __shfl_xor_sync(0xffffffffu, ssum, 2);
            l_i[half] = l_i[half] * corr + ssum;

#pragma unroll
            for (int nt = 0; nt < 8; nt++) {
                o_acc[nt][half * 2 + 0] *= corr;
                o_acc[nt][half * 2 + 1] *= corr;
            }
        }

        // ---- write P (warp-private rows) to smem as tf32 ----
#pragma unroll
        for (int nt = 0; nt < 4; nt++) {
            const int c0 = nt * 8 + tig * 2;
            Ps[warp * 16 + g    ][c0    ] = f2tf32(s[nt][0]);
            Ps[warp * 16 + g    ][c0 + 1] = f2tf32(s[nt][1]);
            Ps[warp * 16 + g + 8][c0    ] = f2tf32(s[nt][2]);
            Ps[warp * 16 + g + 8][c0 + 1] = f2tf32(s[nt][3]);
        }
        __syncwarp();  // Ps rows are warp-private

        // ---- O += P @ V : key dim 32 -> 4 k-chunks, 8 n-tiles (d=64) ----
#pragma unroll
        for (int kc = 0; kc < 4; kc++) {
            uint32_t af[4];
            af[0] = Ps[warp * 16 + g    ][kc * 8 + tig    ];
            af[1] = Ps[warp * 16 + g + 8][kc * 8 + tig    ];
            af[2] = Ps[warp * 16 + g    ][kc * 8 + tig + 4];
            af[3] = Ps[warp * 16 + g + 8][kc * 8 + tig + 4];
            uint32_t bf[8][2];
#pragma unroll
            for (int nt = 0; nt < 8; nt++) {
                bf[nt][0] = Vs[kc * 8 + tig    ][nt * 8 + g];
                bf[nt][1] = Vs[kc * 8 + tig + 4][nt * 8 + g];
            }
#pragma unroll
            for (int nt = 0; nt < 8; nt++)
                mma_tf32(o_acc[nt], af, bf[nt]);
        }
    }

    // ---- epilogue: normalize and store [b][h][s][d] ----
    float* Op = g_att + base;
    const float inv0 = 1.0f / l_i[0];
    const float inv1 = 1.0f / l_i[1];
#pragma unroll
    for (int nt = 0; nt < 8; nt++) {
        const int d0 = nt * 8 + tig * 2;
        Op[(size_t)r_lo * DK_ + d0    ] = o_acc[nt][0] * inv0;
        Op[(size_t)r_lo * DK_ + d0 + 1] = o_acc[nt][1] * inv0;
        Op[(size_t)r_hi * DK_ + d0    ] = o_acc[nt][2] * inv1;
        Op[(size_t)r_hi * DK_ + d0 + 1] = o_acc[nt][3] * inv1;
    }
}

// ---------------------------------------------------------------------------
// Launch
// ---------------------------------------------------------------------------
extern "C" void kernel_launch(void* const* d_in, const int* in_sizes, int n_in,
                              void* d_out, int out_size) {
    (void)in_sizes; (void)n_in; (void)out_size;
    const float* query = (const float*)d_in[0];
    const float* key   = (const float*)d_in[1];
    const float* value = (const float*)d_in[2];
    const float* Wq = (const float*)d_in[4];
    const float* bq = (const float*)d_in[5];
    const float* Wk = (const float*)d_in[6];
    const float* bk = (const float*)d_in[7];
    const float* Wv = (const float*)d_in[8];
    const float* bv = (const float*)d_in[9];
    const float* Wo = (const float*)d_in[10];
    const float* bo = (const float*)d_in[11];
    float* out = (float*)d_out;

    float *qp, *kp, *vp, *attp;
    cudaGetSymbolAddress((void**)&qp,  g_q);
    cudaGetSymbolAddress((void**)&kp,  g_k);
    cudaGetSymbolAddress((void**)&vp,  g_v);
    cudaGetSymbolAddress((void**)&attp, g_att);

    dim3 gg(D_ / GBN, MTOT / GBM);
    gemm_tf32<<<gg, 256>>>(query, Wq, bq, qp, 1);
    gemm_tf32<<<gg, 256>>>(key,   Wk, bk, kp, 1);
    gemm_tf32<<<gg, 256>>>(value, Wv, bv, vp, 1);

    attn_tc<<<dim3(S_ / BQ, H_, B_), 128>>>();

    gemm_tf32<<<gg, 256>>>(attp, Wo, bo, out, 0);
}

// round 6
// speedup vs baseline: 3.7328x; 1.8947x over previous
#include <cuda_runtime.h>
#include <math.h>
#include <stdint.h>

// Problem dims (fixed by the dataset)
#define B_   2
#define S_   2048
#define D_   1024
#define H_   16
#define DK_  64
#define MTOT (B_ * S_)

// ---------------------------------------------------------------------------
// Scratch
// ---------------------------------------------------------------------------
__device__ float g_q[B_ * H_ * S_ * DK_];
__device__ float g_k[B_ * H_ * S_ * DK_];
__device__ float g_v[B_ * H_ * S_ * DK_];
__device__ float g_att[B_ * H_ * S_ * DK_];

__device__ __forceinline__ uint32_t f2tf32(float x) {
    uint32_t r;
    asm("cvt.rna.tf32.f32 %0, %1;" : "=r"(r) : "f"(x));
    return r;
}

__device__ __forceinline__ void mma_tf32(float* d, const uint32_t* a, const uint32_t* b) {
    asm volatile(
        "mma.sync.aligned.m16n8k8.row.col.f32.tf32.tf32.f32 "
        "{%0,%1,%2,%3}, {%4,%5,%6,%7}, {%8,%9}, {%0,%1,%2,%3};"
        : "+f"(d[0]), "+f"(d[1]), "+f"(d[2]), "+f"(d[3])
        : "r"(a[0]), "r"(a[1]), "r"(a[2]), "r"(a[3]), "r"(b[0]), "r"(b[1]));
}

// ---------------------------------------------------------------------------
// TF32 GEMM body, double-buffered software pipeline.
//   C[4096,1024] = A @ W + bias ; CTA tile 128x128, BK=16, 8 warps.
// Numerics identical to R5 (same cvt.rna placement, same accumulation order).
// ---------------------------------------------------------------------------
#define GBM 128
#define GBN 128
#define GBK 16
#define APAD 132

__device__ __forceinline__ void gemm_body(
    const float* __restrict__ A, const float* __restrict__ W,
    const float* __restrict__ bias, float* __restrict__ C, int head_layout) {

    __shared__ uint32_t As[2][GBK][APAD];
    __shared__ uint32_t Bs[2][GBK][APAD];

    const int tid   = threadIdx.x;
    const int wid   = tid >> 5;
    const int lane  = tid & 31;
    const int g     = lane >> 2;
    const int tig   = lane & 3;

    const int warp_m = wid & 3;
    const int warp_n = wid >> 2;

    const int row0 = blockIdx.y * GBM;
    const int col0 = blockIdx.x * GBN;

    // load index precompute (same mapping as R5)
    const int ar0 = (tid + 0)   >> 2, ac0 = ((tid + 0)   & 3) * 4;
    const int ar1 = (tid + 256) >> 2, ac1 = ((tid + 256) & 3) * 4;
    const int wr0 = (tid + 0)   >> 5, wc0 = ((tid + 0)   & 31) * 4;
    const int wr1 = (tid + 256) >> 5, wc1 = ((tid + 256) & 31) * 4;

    float4 arg[2], wrg[2];

    auto load_tile = [&](int kt) {
        arg[0] = *(const float4*)&A[(size_t)(row0 + ar0) * D_ + kt + ac0];
        arg[1] = *(const float4*)&A[(size_t)(row0 + ar1) * D_ + kt + ac1];
        wrg[0] = *(const float4*)&W[(size_t)(kt + wr0) * D_ + col0 + wc0];
        wrg[1] = *(const float4*)&W[(size_t)(kt + wr1) * D_ + col0 + wc1];
    };
    auto store_tile = [&](int buf) {
        As[buf][ac0 + 0][ar0] = f2tf32(arg[0].x);
        As[buf][ac0 + 1][ar0] = f2tf32(arg[0].y);
        As[buf][ac0 + 2][ar0] = f2tf32(arg[0].z);
        As[buf][ac0 + 3][ar0] = f2tf32(arg[0].w);
        As[buf][ac1 + 0][ar1] = f2tf32(arg[1].x);
        As[buf][ac1 + 1][ar1] = f2tf32(arg[1].y);
        As[buf][ac1 + 2][ar1] = f2tf32(arg[1].z);
        As[buf][ac1 + 3][ar1] = f2tf32(arg[1].w);
        uint4 u0, u1;
        u0.x = f2tf32(wrg[0].x); u0.y = f2tf32(wrg[0].y);
        u0.z = f2tf32(wrg[0].z); u0.w = f2tf32(wrg[0].w);
        u1.x = f2tf32(wrg[1].x); u1.y = f2tf32(wrg[1].y);
        u1.z = f2tf32(wrg[1].z); u1.w = f2tf32(wrg[1].w);
        *(uint4*)&Bs[buf][wr0][wc0] = u0;
        *(uint4*)&Bs[buf][wr1][wc1] = u1;
    };

    float acc[2][8][4];
#pragma unroll
    for (int mt = 0; mt < 2; mt++)
#pragma unroll
        for (int nt = 0; nt < 8; nt++)
#pragma unroll
            for (int i = 0; i < 4; i++) acc[mt][nt][i] = 0.0f;

    // prologue
    load_tile(0);
    store_tile(0);
    __syncthreads();

    for (int it = 0; it < D_ / GBK; it++) {
        const int buf = it & 1;
        const bool has_next = (it + 1) < (D_ / GBK);
        if (has_next) load_tile((it + 1) * GBK);

#pragma unroll
        for (int ks = 0; ks < GBK; ks += 8) {
            uint32_t afr[2][4], bfr[8][2];
#pragma unroll
            for (int mt = 0; mt < 2; mt++) {
                const int r0 = warp_m * 32 + mt * 16;
                afr[mt][0] = As[buf][ks + tig    ][r0 + g    ];
                afr[mt][1] = As[buf][ks + tig    ][r0 + g + 8];
                afr[mt][2] = As[buf][ks + tig + 4][r0 + g    ];
                afr[mt][3] = As[buf][ks + tig + 4][r0 + g + 8];
            }
#pragma unroll
            for (int nt = 0; nt < 8; nt++) {
                const int n0 = warp_n * 64 + nt * 8;
                bfr[nt][0] = Bs[buf][ks + tig    ][n0 + g];
                bfr[nt][1] = Bs[buf][ks + tig + 4][n0 + g];
            }
#pragma unroll
            for (int mt = 0; mt < 2; mt++)
#pragma unroll
                for (int nt = 0; nt < 8; nt++)
                    mma_tf32(acc[mt][nt], afr[mt], bfr[nt]);
        }

        if (has_next) {
            store_tile(buf ^ 1);
            __syncthreads();
        }
    }

    // epilogue
#pragma unroll
    for (int mt = 0; mt < 2; mt++) {
#pragma unroll
        for (int nt = 0; nt < 8; nt++) {
            const int cbase = col0 + warp_n * 64 + nt * 8 + tig * 2;
#pragma unroll
            for (int half = 0; half < 2; half++) {
                const int r = row0 + warp_m * 32 + mt * 16 + g + half * 8;
#pragma unroll
                for (int cc = 0; cc < 2; cc++) {
                    const int c = cbase + cc;
                    const float v = acc[mt][nt][half * 2 + cc] + bias[c];
                    if (head_layout) {
                        const int b = r / S_, s = r % S_;
                        const int hh = c / DK_, d = c % DK_;
                        C[(((size_t)(b * H_ + hh)) * S_ + s) * DK_ + d] = v;
                    } else {
                        C[(size_t)r * D_ + c] = v;
                    }
                }
            }
        }
    }
}

// Fused Q/K/V projection: blockIdx.z selects which GEMM.
__global__ __launch_bounds__(256)
void qkv_gemm(const float* __restrict__ q_in, const float* __restrict__ k_in,
              const float* __restrict__ v_in,
              const float* __restrict__ Wq, const float* __restrict__ Wk,
              const float* __restrict__ Wv,
              const float* __restrict__ bq, const float* __restrict__ bk,
              const float* __restrict__ bv,
              float* __restrict__ qo, float* __restrict__ ko,
              float* __restrict__ vo) {
    const int z = blockIdx.z;
    const float* A    = (z == 0) ? q_in : (z == 1) ? k_in : v_in;
    const float* W    = (z == 0) ? Wq   : (z == 1) ? Wk   : Wv;
    const float* bias = (z == 0) ? bq   : (z == 1) ? bk   : bv;
    float*       C    = (z == 0) ? qo   : (z == 1) ? ko   : vo;
    gemm_body(A, W, bias, C, 1);
}

// Output projection (row-major output).
__global__ __launch_bounds__(256)
void out_gemm(const float* __restrict__ A, const float* __restrict__ W,
              const float* __restrict__ bias, float* __restrict__ C) {
    gemm_body(A, W, bias, C, 0);
}

// ---------------------------------------------------------------------------
// Tensor-core flash attention (causal) — unchanged from passing R5.
// ---------------------------------------------------------------------------
#define BQ   64
#define BKA  32
#define KST  68
#define VST  72
#define PST  36

__global__ __launch_bounds__(128)
void attn_tc() {
    __shared__ uint32_t Ks[BKA][KST];
    __shared__ uint32_t Vs[BKA][VST];
    __shared__ uint32_t Ps[BQ][PST];

    const int tid  = threadIdx.x;
    const int warp = tid >> 5;
    const int lane = tid & 31;
    const int g    = lane >> 2;
    const int tig  = lane & 3;

    const int qi = blockIdx.x;
    const int h  = blockIdx.y;
    const int b  = blockIdx.z;
    const size_t base = (size_t)(b * H_ + h) * S_ * DK_;
    const float* Kp = g_k + base;
    const float* Vp = g_v + base;

    const int q0   = qi * BQ;
    const int r_lo = q0 + warp * 16 + g;
    const int r_hi = r_lo + 8;

    uint32_t qf[8][4];
    {
        const float* Qb = g_q + base + (size_t)(q0 + warp * 16) * DK_;
#pragma unroll
        for (int kc = 0; kc < 8; kc++) {
            qf[kc][0] = f2tf32(Qb[(size_t)g       * DK_ + kc * 8 + tig    ]);
            qf[kc][1] = f2tf32(Qb[(size_t)(g + 8) * DK_ + kc * 8 + tig    ]);
            qf[kc][2] = f2tf32(Qb[(size_t)g       * DK_ + kc * 8 + tig + 4]);
            qf[kc][3] = f2tf32(Qb[(size_t)(g + 8) * DK_ + kc * 8 + tig + 4]);
        }
    }

    float m_i[2] = {-1e30f, -1e30f};
    float l_i[2] = {0.0f, 0.0f};
    float o_acc[8][4];
#pragma unroll
    for (int nt = 0; nt < 8; nt++)
#pragma unroll
        for (int i = 0; i < 4; i++) o_acc[nt][i] = 0.0f;

    const float scale = 0.125f;
    const int nkb = (q0 + BQ) / BKA;

    for (int kb = 0; kb < nkb; kb++) {
        const int k0 = kb * BKA;
        __syncthreads();

#pragma unroll
        for (int i = 0; i < 4; i++) {
            const int idx = tid + i * 128;
            const int r   = idx >> 4;
            const int c4  = (idx & 15) * 4;
            float4 kv = *(const float4*)&Kp[(size_t)(k0 + r) * DK_ + c4];
            Ks[r][c4 + 0] = f2tf32(kv.x);
            Ks[r][c4 + 1] = f2tf32(kv.y);
            Ks[r][c4 + 2] = f2tf32(kv.z);
            Ks[r][c4 + 3] = f2tf32(kv.w);
            float4 vv = *(const float4*)&Vp[(size_t)(k0 + r) * DK_ + c4];
            Vs[r][c4 + 0] = f2tf32(vv.x);
            Vs[r][c4 + 1] = f2tf32(vv.y);
            Vs[r][c4 + 2] = f2tf32(vv.z);
            Vs[r][c4 + 3] = f2tf32(vv.w);
        }
        __syncthreads();

        float s[4][4];
#pragma unroll
        for (int nt = 0; nt < 4; nt++)
#pragma unroll
            for (int i = 0; i < 4; i++) s[nt][i] = 0.0f;

#pragma unroll
        for (int kc = 0; kc < 8; kc++) {
            uint32_t bf[4][2];
#pragma unroll
            for (int nt = 0; nt < 4; nt++) {
                bf[nt][0] = Ks[nt * 8 + g][kc * 8 + tig    ];
                bf[nt][1] = Ks[nt * 8 + g][kc * 8 + tig + 4];
            }
#pragma unroll
            for (int nt = 0; nt < 4; nt++)
                mma_tf32(s[nt], qf[kc], bf[nt]);
        }

#pragma unroll
        for (int half = 0; half < 2; half++) {
            const int qg = (half == 0) ? r_lo : r_hi;
            float mx = -1e30f;
#pragma unroll
            for (int nt = 0; nt < 4; nt++) {
#pragma unroll
                for (int cc = 0; cc < 2; cc++) {
                    const int kg = k0 + nt * 8 + tig * 2 + cc;
                    float sv = s[nt][half * 2 + cc] * scale;
                    if (kg > qg) sv = -1e30f;
                    s[nt][half * 2 + cc] = sv;
                    mx = fmaxf(mx, sv);
                }
            }
            mx = fmaxf(mx, __shfl_xor_sync(0xffffffffu, mx, 1));
            mx = fmaxf(mx, __shfl_xor_sync(0xffffffffu, mx, 2));

            const float mnew = fmaxf(m_i[half], mx);
            const float corr = __expf(m_i[half] - mnew);
            m_i[half] = mnew;

            float ssum = 0.0f;
#pragma unroll
            for (int nt = 0; nt < 4; nt++) {
#pragma unroll
                for (int cc = 0; cc < 2; cc++) {
                    const float p = __expf(s[nt][half * 2 + cc] - mnew);
                    s[nt][half * 2 + cc] = p;
                    ssum += p;
                }
            }
            ssum += __shfl_xor_sync(0xffffffffu, ssum, 1);
            ssum += __shfl_xor_sync(0xffffffffu, ssum, 2);
            l_i[half] = l_i[half] * corr + ssum;

#pragma unroll
            for (int nt = 0; nt < 8; nt++) {
                o_acc[nt][half * 2 + 0] *= corr;
                o_acc[nt][half * 2 + 1] *= corr;
            }
        }

#pragma unroll
        for (int nt = 0; nt < 4; nt++) {
            const int c0 = nt * 8 + tig * 2;
            Ps[warp * 16 + g    ][c0    ] = f2tf32(s[nt][0]);
            Ps[warp * 16 + g    ][c0 + 1] = f2tf32(s[nt][1]);
            Ps[warp * 16 + g + 8][c0    ] = f2tf32(s[nt][2]);
            Ps[warp * 16 + g + 8][c0 + 1] = f2tf32(s[nt][3]);
        }
        __syncwarp();

#pragma unroll
        for (int kc = 0; kc < 4; kc++) {
            uint32_t af[4];
            af[0] = Ps[warp * 16 + g    ][kc * 8 + tig    ];
            af[1] = Ps[warp * 16 + g + 8][kc * 8 + tig    ];
            af[2] = Ps[warp * 16 + g    ][kc * 8 + tig + 4];
            af[3] = Ps[warp * 16 + g + 8][kc * 8 + tig + 4];
            uint32_t bf[8][2];
#pragma unroll
            for (int nt = 0; nt < 8; nt++) {
                bf[nt][0] = Vs[kc * 8 + tig    ][nt * 8 + g];
                bf[nt][1] = Vs[kc * 8 + tig + 4][nt * 8 + g];
            }
#pragma unroll
            for (int nt = 0; nt < 8; nt++)
                mma_tf32(o_acc[nt], af, bf[nt]);
        }
    }

    float* Op = g_att + base;
    const float inv0 = 1.0f / l_i[0];
    const float inv1 = 1.0f / l_i[1];
#pragma unroll
    for (int nt = 0; nt < 8; nt++) {
        const int d0 = nt * 8 + tig * 2;
        Op[(size_t)r_lo * DK_ + d0    ] = o_acc[nt][0] * inv0;
        Op[(size_t)r_lo * DK_ + d0 + 1] = o_acc[nt][1] * inv0;
        Op[(size_t)r_hi * DK_ + d0    ] = o_acc[nt][2] * inv1;
        Op[(size_t)r_hi * DK_ + d0 + 1] = o_acc[nt][3] * inv1;
    }
}

// ---------------------------------------------------------------------------
// Launch
// ---------------------------------------------------------------------------
extern "C" void kernel_launch(void* const* d_in, const int* in_sizes, int n_in,
                              void* d_out, int out_size) {
    (void)in_sizes; (void)n_in; (void)out_size;
    const float* query = (const float*)d_in[0];
    const float* key   = (const float*)d_in[1];
    const float* value = (const float*)d_in[2];
    const float* Wq = (const float*)d_in[4];
    const float* bq = (const float*)d_in[5];
    const float* Wk = (const float*)d_in[6];
    const float* bk = (const float*)d_in[7];
    const float* Wv = (const float*)d_in[8];
    const float* bv = (const float*)d_in[9];
    const float* Wo = (const float*)d_in[10];
    const float* bo = (const float*)d_in[11];
    float* out = (float*)d_out;

    float *qp, *kp, *vp, *attp;
    cudaGetSymbolAddress((void**)&qp,  g_q);
    cudaGetSymbolAddress((void**)&kp,  g_k);
    cudaGetSymbolAddress((void**)&vp,  g_v);
    cudaGetSymbolAddress((void**)&attp, g_att);

    dim3 gqkv(D_ / GBN, MTOT / GBM, 3);   // (8, 32, 3) = 768 CTAs
    qkv_gemm<<<gqkv, 256>>>(query, key, value, Wq, Wk, Wv, bq, bk, bv, qp, kp, vp);

    attn_tc<<<dim3(S_ / BQ, H_, B_), 128>>>();

    out_gemm<<<dim3(D_ / GBN, MTOT / GBM), 256>>>(attp, Wo, bo, out);
}

// round 7
// speedup vs baseline: 4.6701x; 1.2511x over previous
#include <cuda_runtime.h>
#include <math.h>
#include <stdint.h>

// Problem dims (fixed by the dataset)
#define B_   2
#define S_   2048
#define D_   1024
#define H_   16
#define DK_  64
#define MTOT (B_ * S_)

// ---------------------------------------------------------------------------
// Scratch
// ---------------------------------------------------------------------------
__device__ float g_q[B_ * H_ * S_ * DK_];
__device__ float g_k[B_ * H_ * S_ * DK_];
__device__ float g_v[B_ * H_ * S_ * DK_];
__device__ float g_att[B_ * H_ * S_ * DK_];

__device__ __forceinline__ uint32_t f2tf32(float x) {
    uint32_t r;
    asm("cvt.rna.tf32.f32 %0, %1;" : "=r"(r) : "f"(x));
    return r;
}

__device__ __forceinline__ void mma_tf32(float* d, const uint32_t* a, const uint32_t* b) {
    asm volatile(
        "mma.sync.aligned.m16n8k8.row.col.f32.tf32.tf32.f32 "
        "{%0,%1,%2,%3}, {%4,%5,%6,%7}, {%8,%9}, {%0,%1,%2,%3};"
        : "+f"(d[0]), "+f"(d[1]), "+f"(d[2]), "+f"(d[3])
        : "r"(a[0]), "r"(a[1]), "r"(a[2]), "r"(a[3]), "r"(b[0]), "r"(b[1]));
}

__device__ __forceinline__ uint32_t smem_u32(const void* p) {
    return (uint32_t)__cvta_generic_to_shared(p);
}

__device__ __forceinline__ void cp_async16(uint32_t dst, const void* src) {
    asm volatile("cp.async.cg.shared.global [%0], [%1], 16;\n" :: "r"(dst), "l"(src));
}
__device__ __forceinline__ void cp_commit() {
    asm volatile("cp.async.commit_group;\n");
}
template <int N>
__device__ __forceinline__ void cp_wait() {
    asm volatile("cp.async.wait_group %0;\n" :: "n"(N));
}

// ---------------------------------------------------------------------------
// TF32 GEMM body: cp.async 2-stage pipeline.
//   C[4096,1024] = A @ W + bias ; CTA tile 128x128, BK=16, 8 warps, 2 CTA/SM.
// A smem [m][k] stride 20 (cp.async friendly; frag banks 20g+tig all distinct).
// B smem [k][n] stride 132 (direct row copy).
// f2tf32 applied at fragment load -> numerics bit-identical to R5/R6.
// ---------------------------------------------------------------------------
#define GBM 128
#define GBN 128
#define GBK 16
#define AST 20
#define BST 132

__device__ __forceinline__ void gemm_body(
    const float* __restrict__ A, const float* __restrict__ W,
    const float* __restrict__ bias, float* __restrict__ C, int head_layout) {

    __shared__ float As[2][GBM][AST];   // 20480 B
    __shared__ float Bs[2][GBK][BST];   // 16896 B  (37376 total)

    const int tid   = threadIdx.x;
    const int wid   = tid >> 5;
    const int lane  = tid & 31;
    const int g     = lane >> 2;
    const int tig   = lane & 3;

    const int warp_m = wid & 3;
    const int warp_n = wid >> 2;

    const int row0 = blockIdx.y * GBM;
    const int col0 = blockIdx.x * GBN;

    // A chunk mapping: 512 chunks of 16B; chunk c -> row c>>2, kcol (c&3)*4
    const int a_r0 = (tid + 0)   >> 2, a_k0 = ((tid + 0)   & 3) * 4;
    const int a_r1 = (tid + 256) >> 2, a_k1 = ((tid + 256) & 3) * 4;
    // B chunk mapping: 512 chunks; chunk c -> krow c>>5, ncol (c&31)*4
    const int b_k0 = (tid + 0)   >> 5, b_n0 = ((tid + 0)   & 31) * 4;
    const int b_k1 = (tid + 256) >> 5, b_n1 = ((tid + 256) & 31) * 4;

    auto issue_tile = [&](int kt, int buf) {
        cp_async16(smem_u32(&As[buf][a_r0][a_k0]),
                   &A[(size_t)(row0 + a_r0) * D_ + kt + a_k0]);
        cp_async16(smem_u32(&As[buf][a_r1][a_k1]),
                   &A[(size_t)(row0 + a_r1) * D_ + kt + a_k1]);
        cp_async16(smem_u32(&Bs[buf][b_k0][b_n0]),
                   &W[(size_t)(kt + b_k0) * D_ + col0 + b_n0]);
        cp_async16(smem_u32(&Bs[buf][b_k1][b_n1]),
                   &W[(size_t)(kt + b_k1) * D_ + col0 + b_n1]);
        cp_commit();
    };

    float acc[2][8][4];
#pragma unroll
    for (int mt = 0; mt < 2; mt++)
#pragma unroll
        for (int nt = 0; nt < 8; nt++)
#pragma unroll
            for (int i = 0; i < 4; i++) acc[mt][nt][i] = 0.0f;

    const int NT = D_ / GBK;
    issue_tile(0, 0);

    for (int it = 0; it < NT; it++) {
        const int buf = it & 1;
        const bool has_next = (it + 1) < NT;
        if (has_next) {
            issue_tile((it + 1) * GBK, buf ^ 1);
            cp_wait<1>();
        } else {
            cp_wait<0>();
        }
        __syncthreads();

#pragma unroll
        for (int ks = 0; ks < GBK; ks += 8) {
            uint32_t afr[2][4], bfr[8][2];
#pragma unroll
            for (int mt = 0; mt < 2; mt++) {
                const int r0 = warp_m * 32 + mt * 16;
                afr[mt][0] = f2tf32(As[buf][r0 + g    ][ks + tig    ]);
                afr[mt][1] = f2tf32(As[buf][r0 + g + 8][ks + tig    ]);
                afr[mt][2] = f2tf32(As[buf][r0 + g    ][ks + tig + 4]);
                afr[mt][3] = f2tf32(As[buf][r0 + g + 8][ks + tig + 4]);
            }
#pragma unroll
            for (int nt = 0; nt < 8; nt++) {
                const int n0 = warp_n * 64 + nt * 8;
                bfr[nt][0] = f2tf32(Bs[buf][ks + tig    ][n0 + g]);
                bfr[nt][1] = f2tf32(Bs[buf][ks + tig + 4][n0 + g]);
            }
#pragma unroll
            for (int mt = 0; mt < 2; mt++)
#pragma unroll
                for (int nt = 0; nt < 8; nt++)
                    mma_tf32(acc[mt][nt], afr[mt], bfr[nt]);
        }
        __syncthreads();  // all reads of buf done before next issue into it
    }

    // epilogue
#pragma unroll
    for (int mt = 0; mt < 2; mt++) {
#pragma unroll
        for (int nt = 0; nt < 8; nt++) {
            const int cbase = col0 + warp_n * 64 + nt * 8 + tig * 2;
#pragma unroll
            for (int half = 0; half < 2; half++) {
                const int r = row0 + warp_m * 32 + mt * 16 + g + half * 8;
#pragma unroll
                for (int cc = 0; cc < 2; cc++) {
                    const int c = cbase + cc;
                    const float v = acc[mt][nt][half * 2 + cc] + bias[c];
                    if (head_layout) {
                        const int b = r / S_, s = r % S_;
                        const int hh = c / DK_, d = c % DK_;
                        C[(((size_t)(b * H_ + hh)) * S_ + s) * DK_ + d] = v;
                    } else {
                        C[(size_t)r * D_ + c] = v;
                    }
                }
            }
        }
    }
}

// Fused Q/K/V projection: blockIdx.z selects which GEMM.
__global__ __launch_bounds__(256, 2)
void qkv_gemm(const float* __restrict__ q_in, const float* __restrict__ k_in,
              const float* __restrict__ v_in,
              const float* __restrict__ Wq, const float* __restrict__ Wk,
              const float* __restrict__ Wv,
              const float* __restrict__ bq, const float* __restrict__ bk,
              const float* __restrict__ bv,
              float* __restrict__ qo, float* __restrict__ ko,
              float* __restrict__ vo) {
    const int z = blockIdx.z;
    const float* A    = (z == 0) ? q_in : (z == 1) ? k_in : v_in;
    const float* W    = (z == 0) ? Wq   : (z == 1) ? Wk   : Wv;
    const float* bias = (z == 0) ? bq   : (z == 1) ? bk   : bv;
    float*       C    = (z == 0) ? qo   : (z == 1) ? ko   : vo;
    gemm_body(A, W, bias, C, 1);
}

// Output projection (row-major output).
__global__ __launch_bounds__(256, 2)
void out_gemm(const float* __restrict__ A, const float* __restrict__ W,
              const float* __restrict__ bias, float* __restrict__ C) {
    gemm_body(A, W, bias, C, 0);
}

// ---------------------------------------------------------------------------
// Tensor-core flash attention (causal) — unchanged from passing R5/R6.
// ---------------------------------------------------------------------------
#define BQ   64
#define BKA  32
#define KST  68
#define VST  72
#define PST  36

__global__ __launch_bounds__(128)
void attn_tc() {
    __shared__ uint32_t Ks[BKA][KST];
    __shared__ uint32_t Vs[BKA][VST];
    __shared__ uint32_t Ps[BQ][PST];

    const int tid  = threadIdx.x;
    const int warp = tid >> 5;
    const int lane = tid & 31;
    const int g    = lane >> 2;
    const int tig  = lane & 3;

    const int qi = blockIdx.x;
    const int h  = blockIdx.y;
    const int b  = blockIdx.z;
    const size_t base = (size_t)(b * H_ + h) * S_ * DK_;
    const float* Kp = g_k + base;
    const float* Vp = g_v + base;

    const int q0   = qi * BQ;
    const int r_lo = q0 + warp * 16 + g;
    const int r_hi = r_lo + 8;

    uint32_t qf[8][4];
    {
        const float* Qb = g_q + base + (size_t)(q0 + warp * 16) * DK_;
#pragma unroll
        for (int kc = 0; kc < 8; kc++) {
            qf[kc][0] = f2tf32(Qb[(size_t)g       * DK_ + kc * 8 + tig    ]);
            qf[kc][1] = f2tf32(Qb[(size_t)(g + 8) * DK_ + kc * 8 + tig    ]);
            qf[kc][2] = f2tf32(Qb[(size_t)g       * DK_ + kc * 8 + tig + 4]);
            qf[kc][3] = f2tf32(Qb[(size_t)(g + 8) * DK_ + kc * 8 + tig + 4]);
        }
    }

    float m_i[2] = {-1e30f, -1e30f};
    float l_i[2] = {0.0f, 0.0f};
    float o_acc[8][4];
#pragma unroll
    for (int nt = 0; nt < 8; nt++)
#pragma unroll
        for (int i = 0; i < 4; i++) o_acc[nt][i] = 0.0f;

    const float scale = 0.125f;
    const int nkb = (q0 + BQ) / BKA;

    for (int kb = 0; kb < nkb; kb++) {
        const int k0 = kb * BKA;
        __syncthreads();

#pragma unroll
        for (int i = 0; i < 4; i++) {
            const int idx = tid + i * 128;
            const int r   = idx >> 4;
            const int c4  = (idx & 15) * 4;
            float4 kv = *(const float4*)&Kp[(size_t)(k0 + r) * DK_ + c4];
            Ks[r][c4 + 0] = f2tf32(kv.x);
            Ks[r][c4 + 1] = f2tf32(kv.y);
            Ks[r][c4 + 2] = f2tf32(kv.z);
            Ks[r][c4 + 3] = f2tf32(kv.w);
            float4 vv = *(const float4*)&Vp[(size_t)(k0 + r) * DK_ + c4];
            Vs[r][c4 + 0] = f2tf32(vv.x);
            Vs[r][c4 + 1] = f2tf32(vv.y);
            Vs[r][c4 + 2] = f2tf32(vv.z);
            Vs[r][c4 + 3] = f2tf32(vv.w);
        }
        __syncthreads();

        float s[4][4];
#pragma unroll
        for (int nt = 0; nt < 4; nt++)
#pragma unroll
            for (int i = 0; i < 4; i++) s[nt][i] = 0.0f;

#pragma unroll
        for (int kc = 0; kc < 8; kc++) {
            uint32_t bf[4][2];
#pragma unroll
            for (int nt = 0; nt < 4; nt++) {
                bf[nt][0] = Ks[nt * 8 + g][kc * 8 + tig    ];
                bf[nt][1] = Ks[nt * 8 + g][kc * 8 + tig + 4];
            }
#pragma unroll
            for (int nt = 0; nt < 4; nt++)
                mma_tf32(s[nt], qf[kc], bf[nt]);
        }

#pragma unroll
        for (int half = 0; half < 2; half++) {
            const int qg = (half == 0) ? r_lo : r_hi;
            float mx = -1e30f;
#pragma unroll
            for (int nt = 0; nt < 4; nt++) {
#pragma unroll
                for (int cc = 0; cc < 2; cc++) {
                    const int kg = k0 + nt * 8 + tig * 2 + cc;
                    float sv = s[nt][half * 2 + cc] * scale;
                    if (kg > qg) sv = -1e30f;
                    s[nt][half * 2 + cc] = sv;
                    mx = fmaxf(mx, sv);
                }
            }
            mx = fmaxf(mx, __shfl_xor_sync(0xffffffffu, mx, 1));
            mx = fmaxf(mx, __shfl_xor_sync(0xffffffffu, mx, 2));

            const float mnew = fmaxf(m_i[half], mx);
            const float corr = __expf(m_i[half] - mnew);
            m_i[half] = mnew;

            float ssum = 0.0f;
#pragma unroll
            for (int nt = 0; nt < 4; nt++) {
#pragma unroll
                for (int cc = 0; cc < 2; cc++) {
                    const float p = __expf(s[nt][half * 2 + cc] - mnew);
                    s[nt][half * 2 + cc] = p;
                    ssum += p;
                }
            }
            ssum += __shfl_xor_sync(0xffffffffu, ssum, 1);
            ssum += __shfl_xor_sync(0xffffffffu, ssum, 2);
            l_i[half] = l_i[half] * corr + ssum;

#pragma unroll
            for (int nt = 0; nt < 8; nt++) {
                o_acc[nt][half * 2 + 0] *= corr;
                o_acc[nt][half * 2 + 1] *= corr;
            }
        }

#pragma unroll
        for (int nt = 0; nt < 4; nt++) {
            const int c0 = nt * 8 + tig * 2;
            Ps[warp * 16 + g    ][c0    ] = f2tf32(s[nt][0]);
            Ps[warp * 16 + g    ][c0 + 1] = f2tf32(s[nt][1]);
            Ps[warp * 16 + g + 8][c0    ] = f2tf32(s[nt][2]);
            Ps[warp * 16 + g + 8][c0 + 1] = f2tf32(s[nt][3]);
        }
        __syncwarp();

#pragma unroll
        for (int kc = 0; kc < 4; kc++) {
            uint32_t af[4];
            af[0] = Ps[warp * 16 + g    ][kc * 8 + tig    ];
            af[1] = Ps[warp * 16 + g + 8][kc * 8 + tig    ];
            af[2] = Ps[warp * 16 + g    ][kc * 8 + tig + 4];
            af[3] = Ps[warp * 16 + g + 8][kc * 8 + tig + 4];
            uint32_t bf[8][2];
#pragma unroll
            for (int nt = 0; nt < 8; nt++) {
                bf[nt][0] = Vs[kc * 8 + tig    ][nt * 8 + g];
                bf[nt][1] = Vs[kc * 8 + tig + 4][nt * 8 + g];
            }
#pragma unroll
            for (int nt = 0; nt < 8; nt++)
                mma_tf32(o_acc[nt], af, bf[nt]);
        }
    }

    float* Op = g_att + base;
    const float inv0 = 1.0f / l_i[0];
    const float inv1 = 1.0f / l_i[1];
#pragma unroll
    for (int nt = 0; nt < 8; nt++) {
        const int d0 = nt * 8 + tig * 2;
        Op[(size_t)r_lo * DK_ + d0    ] = o_acc[nt][0] * inv0;
        Op[(size_t)r_lo * DK_ + d0 + 1] = o_acc[nt][1] * inv0;
        Op[(size_t)r_hi * DK_ + d0    ] = o_acc[nt][2] * inv1;
        Op[(size_t)r_hi * DK_ + d0 + 1] = o_acc[nt][3] * inv1;
    }
}

// ---------------------------------------------------------------------------
// Launch
// ---------------------------------------------------------------------------
extern "C" void kernel_launch(void* const* d_in, const int* in_sizes, int n_in,
                              void* d_out, int out_size) {
    (void)in_sizes; (void)n_in; (void)out_size;
    const float* query = (const float*)d_in[0];
    const float* key   = (const float*)d_in[1];
    const float* value = (const float*)d_in[2];
    const float* Wq = (const float*)d_in[4];
    const float* bq = (const float*)d_in[5];
    const float* Wk = (const float*)d_in[6];
    const float* bk = (const float*)d_in[7];
    const float* Wv = (const float*)d_in[8];
    const float* bv = (const float*)d_in[9];
    const float* Wo = (const float*)d_in[10];
    const float* bo = (const float*)d_in[11];
    float* out = (float*)d_out;

    float *qp, *kp, *vp, *attp;
    cudaGetSymbolAddress((void**)&qp,  g_q);
    cudaGetSymbolAddress((void**)&kp,  g_k);
    cudaGetSymbolAddress((void**)&vp,  g_v);
    cudaGetSymbolAddress((void**)&attp, g_att);

    dim3 gqkv(D_ / GBN, MTOT / GBM, 3);   // (8, 32, 3) = 768 CTAs
    qkv_gemm<<<gqkv, 256>>>(query, key, value, Wq, Wk, Wv, bq, bk, bv, qp, kp, vp);

    attn_tc<<<dim3(S_ / BQ, H_, B_), 128>>>();

    out_gemm<<<dim3(D_ / GBN, MTOT / GBM), 256>>>(attp, Wo, bo, out);
}

// round 8
// speedup vs baseline: 5.0233x; 1.0756x over previous
#include <cuda_runtime.h>
#include <math.h>
#include <stdint.h>

// Problem dims (fixed by the dataset)
#define B_   2
#define S_   2048
#define D_   1024
#define H_   16
#define DK_  64
#define MTOT (B_ * S_)

// ---------------------------------------------------------------------------
// Scratch (tf32 bit patterns stored as uint32)
// ---------------------------------------------------------------------------
__device__ uint32_t g_q[B_ * H_ * S_ * DK_];
__device__ uint32_t g_k[B_ * H_ * S_ * DK_];
__device__ uint32_t g_v[B_ * H_ * S_ * DK_];
__device__ uint32_t g_att[B_ * H_ * S_ * DK_];
__device__ uint32_t g_wq[D_ * D_];
__device__ uint32_t g_wk[D_ * D_];
__device__ uint32_t g_wv[D_ * D_];
__device__ uint32_t g_wo[D_ * D_];

__device__ __forceinline__ uint32_t f2tf32(float x) {
    uint32_t r;
    asm("cvt.rna.tf32.f32 %0, %1;" : "=r"(r) : "f"(x));
    return r;
}

__device__ __forceinline__ void mma_tf32(float* d, const uint32_t* a, const uint32_t* b) {
    asm volatile(
        "mma.sync.aligned.m16n8k8.row.col.f32.tf32.tf32.f32 "
        "{%0,%1,%2,%3}, {%4,%5,%6,%7}, {%8,%9}, {%0,%1,%2,%3};"
        : "+f"(d[0]), "+f"(d[1]), "+f"(d[2]), "+f"(d[3])
        : "r"(a[0]), "r"(a[1]), "r"(a[2]), "r"(a[3]), "r"(b[0]), "r"(b[1]));
}

__device__ __forceinline__ uint32_t smem_u32(const void* p) {
    return (uint32_t)__cvta_generic_to_shared(p);
}
__device__ __forceinline__ void cp_async16(uint32_t dst, const void* src) {
    asm volatile("cp.async.cg.shared.global [%0], [%1], 16;\n" :: "r"(dst), "l"(src));
}
__device__ __forceinline__ void cp_commit() {
    asm volatile("cp.async.commit_group;\n");
}
template <int N>
__device__ __forceinline__ void cp_wait() {
    asm volatile("cp.async.wait_group %0;\n" :: "n"(N));
}

// ---------------------------------------------------------------------------
// Weight pre-conversion: fp32 -> tf32 bits (once per launch, ~6 us)
// ---------------------------------------------------------------------------
__global__ __launch_bounds__(256)
void cvt_weights(const float* __restrict__ wq, const float* __restrict__ wk,
                 const float* __restrict__ wv, const float* __restrict__ wo) {
    const int z = blockIdx.y;
    const float* src = (z == 0) ? wq : (z == 1) ? wk : (z == 2) ? wv : wo;
    uint32_t*    dst = (z == 0) ? g_wq : (z == 1) ? g_wk : (z == 2) ? g_wv : g_wo;
    const int i = (blockIdx.x * 256 + threadIdx.x) * 4;
    float4 v = *(const float4*)&src[i];
    uint4 u;
    u.x = f2tf32(v.x); u.y = f2tf32(v.y); u.z = f2tf32(v.z); u.w = f2tf32(v.w);
    *(uint4*)&dst[i] = u;
}

// ---------------------------------------------------------------------------
// TF32 GEMM body: cp.async 2-stage pipeline, conflict-free smem.
//   A_TF32:   A operand already tf32 bits (no cvt at frag load)
//   HEAD_OUT: write C as tf32 bits in [b][h][s][d] layout; else fp32 row-major
// B operand is ALWAYS pre-converted tf32 bits.
// ---------------------------------------------------------------------------
#define GBM 128
#define GBN 128
#define GBK 16
#define AST 20    // 20 % 32 = 4  -> A-frag banks 20g+tig (all distinct)
#define BST 136   // 136 % 32 = 8 -> B-frag banks 8*tig+g (all distinct; fixes R7 2-way conflict)

template <bool A_TF32, bool HEAD_OUT>
__device__ __forceinline__ void gemm_body(
    const uint32_t* __restrict__ A, const uint32_t* __restrict__ W,
    const float* __restrict__ bias, void* __restrict__ Cv) {

    __shared__ uint32_t As[2][GBM][AST];   // 20480 B
    __shared__ uint32_t Bs[2][GBK][BST];   // 17408 B (37888 total)

    const int tid   = threadIdx.x;
    const int wid   = tid >> 5;
    const int lane  = tid & 31;
    const int g     = lane >> 2;
    const int tig   = lane & 3;

    const int warp_m = wid & 3;
    const int warp_n = wid >> 2;

    const int row0 = blockIdx.y * GBM;
    const int col0 = blockIdx.x * GBN;

    const int a_r0 = (tid + 0)   >> 2, a_k0 = ((tid + 0)   & 3) * 4;
    const int a_r1 = (tid + 256) >> 2, a_k1 = ((tid + 256) & 3) * 4;
    const int b_k0 = (tid + 0)   >> 5, b_n0 = ((tid + 0)   & 31) * 4;
    const int b_k1 = (tid + 256) >> 5, b_n1 = ((tid + 256) & 31) * 4;

    auto issue_tile = [&](int kt, int buf) {
        cp_async16(smem_u32(&As[buf][a_r0][a_k0]),
                   &A[(size_t)(row0 + a_r0) * D_ + kt + a_k0]);
        cp_async16(smem_u32(&As[buf][a_r1][a_k1]),
                   &A[(size_t)(row0 + a_r1) * D_ + kt + a_k1]);
        cp_async16(smem_u32(&Bs[buf][b_k0][b_n0]),
                   &W[(size_t)(kt + b_k0) * D_ + col0 + b_n0]);
        cp_async16(smem_u32(&Bs[buf][b_k1][b_n1]),
                   &W[(size_t)(kt + b_k1) * D_ + col0 + b_n1]);
        cp_commit();
    };

    float acc[2][8][4];
#pragma unroll
    for (int mt = 0; mt < 2; mt++)
#pragma unroll
        for (int nt = 0; nt < 8; nt++)
#pragma unroll
            for (int i = 0; i < 4; i++) acc[mt][nt][i] = 0.0f;

    const int NT = D_ / GBK;
    issue_tile(0, 0);

    for (int it = 0; it < NT; it++) {
        const int buf = it & 1;
        const bool has_next = (it + 1) < NT;
        if (has_next) {
            issue_tile((it + 1) * GBK, buf ^ 1);
            cp_wait<1>();
        } else {
            cp_wait<0>();
        }
        __syncthreads();

#pragma unroll
        for (int ks = 0; ks < GBK; ks += 8) {
            uint32_t afr[2][4], bfr[8][2];
#pragma unroll
            for (int mt = 0; mt < 2; mt++) {
                const int r0 = warp_m * 32 + mt * 16;
                uint32_t a0 = As[buf][r0 + g    ][ks + tig    ];
                uint32_t a1 = As[buf][r0 + g + 8][ks + tig    ];
                uint32_t a2 = As[buf][r0 + g    ][ks + tig + 4];
                uint32_t a3 = As[buf][r0 + g + 8][ks + tig + 4];
                if (!A_TF32) {
                    a0 = f2tf32(__uint_as_float(a0));
                    a1 = f2tf32(__uint_as_float(a1));
                    a2 = f2tf32(__uint_as_float(a2));
                    a3 = f2tf32(__uint_as_float(a3));
                }
                afr[mt][0] = a0; afr[mt][1] = a1; afr[mt][2] = a2; afr[mt][3] = a3;
            }
#pragma unroll
            for (int nt = 0; nt < 8; nt++) {
                const int n0 = warp_n * 64 + nt * 8;
                bfr[nt][0] = Bs[buf][ks + tig    ][n0 + g];
                bfr[nt][1] = Bs[buf][ks + tig + 4][n0 + g];
            }
#pragma unroll
            for (int mt = 0; mt < 2; mt++)
#pragma unroll
                for (int nt = 0; nt < 8; nt++)
                    mma_tf32(acc[mt][nt], afr[mt], bfr[nt]);
        }
        __syncthreads();
    }

    // epilogue
#pragma unroll
    for (int mt = 0; mt < 2; mt++) {
#pragma unroll
        for (int nt = 0; nt < 8; nt++) {
            const int cbase = col0 + warp_n * 64 + nt * 8 + tig * 2;
#pragma unroll
            for (int half = 0; half < 2; half++) {
                const int r = row0 + warp_m * 32 + mt * 16 + g + half * 8;
#pragma unroll
                for (int cc = 0; cc < 2; cc++) {
                    const int c = cbase + cc;
                    const float v = acc[mt][nt][half * 2 + cc] + bias[c];
                    if (HEAD_OUT) {
                        const int b = r / S_, s = r % S_;
                        const int hh = c / DK_, d = c % DK_;
                        ((uint32_t*)Cv)[(((size_t)(b * H_ + hh)) * S_ + s) * DK_ + d] =
                            f2tf32(v);
                    } else {
                        ((float*)Cv)[(size_t)r * D_ + c] = v;
                    }
                }
            }
        }
    }
}

// Fused Q/K/V projection (A = fp32 input, C = tf32-bit head layout).
__global__ __launch_bounds__(256, 2)
void qkv_gemm(const float* __restrict__ q_in, const float* __restrict__ k_in,
              const float* __restrict__ v_in,
              const float* __restrict__ bq, const float* __restrict__ bk,
              const float* __restrict__ bv) {
    const int z = blockIdx.z;
    const uint32_t* A    = (const uint32_t*)((z == 0) ? q_in : (z == 1) ? k_in : v_in);
    const uint32_t* W    = (z == 0) ? g_wq : (z == 1) ? g_wk : g_wv;
    const float*    bias = (z == 0) ? bq   : (z == 1) ? bk   : bv;
    uint32_t*       C    = (z == 0) ? g_q  : (z == 1) ? g_k  : g_v;
    gemm_body<false, true>(A, W, bias, C);
}

// Output projection: A and W already tf32 bits -> zero cvts in hot loop.
__global__ __launch_bounds__(256, 2)
void out_gemm(const float* __restrict__ bias, float* __restrict__ C) {
    gemm_body<true, false>(g_att, g_wo, bias, C);
}

// ---------------------------------------------------------------------------
// Tensor-core flash attention (causal): inputs are tf32 bits, cp.async
// double-buffered K/V tiles, fragment softmax in fp32.
// ---------------------------------------------------------------------------
#define BQ   64
#define BKA  32
#define KST  68   // 68%32=4  -> K-frag banks 4g+tig (distinct)
#define VST  72   // 72%32=8  -> V-frag banks 8tig+g (distinct)
#define PST  36   // 36%32=4  -> P A-frag banks 4g+tig (distinct)

__global__ __launch_bounds__(128)
void attn_tc() {
    __shared__ uint32_t Ks[2][BKA][KST];  // 17408 B
    __shared__ uint32_t Vs[2][BKA][VST];  // 18432 B
    __shared__ uint32_t Ps[BQ][PST];      //  9216 B  (45056 total, < 48K)

    const int tid  = threadIdx.x;
    const int warp = tid >> 5;
    const int lane = tid & 31;
    const int g    = lane >> 2;
    const int tig  = lane & 3;

    const int qi = blockIdx.x;
    const int h  = blockIdx.y;
    const int b  = blockIdx.z;
    const size_t base = (size_t)(b * H_ + h) * S_ * DK_;
    const uint32_t* Kp = g_k + base;
    const uint32_t* Vp = g_v + base;

    const int q0   = qi * BQ;
    const int r_lo = q0 + warp * 16 + g;
    const int r_hi = r_lo + 8;

    // Q fragments (already tf32 bits — direct loads)
    uint32_t qf[8][4];
    {
        const uint32_t* Qb = g_q + base + (size_t)(q0 + warp * 16) * DK_;
#pragma unroll
        for (int kc = 0; kc < 8; kc++) {
            qf[kc][0] = Qb[(size_t)g       * DK_ + kc * 8 + tig    ];
            qf[kc][1] = Qb[(size_t)(g + 8) * DK_ + kc * 8 + tig    ];
            qf[kc][2] = Qb[(size_t)g       * DK_ + kc * 8 + tig + 4];
            qf[kc][3] = Qb[(size_t)(g + 8) * DK_ + kc * 8 + tig + 4];
        }
    }

    auto issue_kv = [&](int kb, int buf) {
        const int k0 = kb * BKA;
#pragma unroll
        for (int i = 0; i < 4; i++) {
            const int idx = tid + i * 128;
            const int r   = idx >> 4;
            const int c4  = (idx & 15) * 4;
            cp_async16(smem_u32(&Ks[buf][r][c4]), &Kp[(size_t)(k0 + r) * DK_ + c4]);
            cp_async16(smem_u32(&Vs[buf][r][c4]), &Vp[(size_t)(k0 + r) * DK_ + c4]);
        }
        cp_commit();
    };

    float m_i[2] = {-1e30f, -1e30f};
    float l_i[2] = {0.0f, 0.0f};
    float o_acc[8][4];
#pragma unroll
    for (int nt = 0; nt < 8; nt++)
#pragma unroll
        for (int i = 0; i < 4; i++) o_acc[nt][i] = 0.0f;

    const float scale = 0.125f;
    const int nkb = (q0 + BQ) / BKA;

    issue_kv(0, 0);

    for (int kb = 0; kb < nkb; kb++) {
        const int k0  = kb * BKA;
        const int buf = kb & 1;
        if (kb + 1 < nkb) {
            issue_kv(kb + 1, buf ^ 1);   // target buf was last read at kb-1 (barrier below)
            cp_wait<1>();
        } else {
            cp_wait<0>();
        }
        __syncthreads();

        // ---- S = Q @ K^T ----
        float s[4][4];
#pragma unroll
        for (int nt = 0; nt < 4; nt++)
#pragma unroll
            for (int i = 0; i < 4; i++) s[nt][i] = 0.0f;

#pragma unroll
        for (int kc = 0; kc < 8; kc++) {
            uint32_t bf[4][2];
#pragma unroll
            for (int nt = 0; nt < 4; nt++) {
                bf[nt][0] = Ks[buf][nt * 8 + g][kc * 8 + tig    ];
                bf[nt][1] = Ks[buf][nt * 8 + g][kc * 8 + tig + 4];
            }
#pragma unroll
            for (int nt = 0; nt < 4; nt++)
                mma_tf32(s[nt], qf[kc], bf[nt]);
        }

        // ---- scale + causal mask + online softmax ----
#pragma unroll
        for (int half = 0; half < 2; half++) {
            const int qg = (half == 0) ? r_lo : r_hi;
            float mx = -1e30f;
#pragma unroll
            for (int nt = 0; nt < 4; nt++) {
#pragma unroll
                for (int cc = 0; cc < 2; cc++) {
                    const int kg = k0 + nt * 8 + tig * 2 + cc;
                    float sv = s[nt][half * 2 + cc] * scale;
                    if (kg > qg) sv = -1e30f;
                    s[nt][half * 2 + cc] = sv;
                    mx = fmaxf(mx, sv);
                }
            }
            mx = fmaxf(mx, __shfl_xor_sync(0xffffffffu, mx, 1));
            mx = fmaxf(mx, __shfl_xor_sync(0xffffffffu, mx, 2));

            const float mnew = fmaxf(m_i[half], mx);
            const float corr = __expf(m_i[half] - mnew);
            m_i[half] = mnew;

            float ssum = 0.0f;
#pragma unroll
            for (int nt = 0; nt < 4; nt++) {
#pragma unroll
                for (int cc = 0; cc < 2; cc++) {
                    const float p = __expf(s[nt][half * 2 + cc] - mnew);
                    s[nt][half * 2 + cc] = p;
                    ssum += p;
                }
            }
            ssum += __shfl_xor_sync(0xffffffffu, ssum, 1);
            ssum += __shfl_xor_sync(0xffffffffu, ssum, 2);
            l_i[half] = l_i[half] * corr + ssum;

#pragma unroll
            for (int nt = 0; nt < 8; nt++) {
                o_acc[nt][half * 2 + 0] *= corr;
                o_acc[nt][half * 2 + 1] *= corr;
            }
        }

        // ---- P to smem (warp-private rows) ----
#pragma unroll
        for (int nt = 0; nt < 4; nt++) {
            const int c0 = nt * 8 + tig * 2;
            Ps[warp * 16 + g    ][c0    ] = f2tf32(s[nt][0]);
            Ps[warp * 16 + g    ][c0 + 1] = f2tf32(s[nt][1]);
            Ps[warp * 16 + g + 8][c0    ] = f2tf32(s[nt][2]);
            Ps[warp * 16 + g + 8][c0 + 1] = f2tf32(s[nt][3]);
        }
        __syncwarp();

        // ---- O += P @ V ----
#pragma unroll
        for (int kc = 0; kc < 4; kc++) {
            uint32_t af[4];
            af[0] = Ps[warp * 16 + g    ][kc * 8 + tig    ];
            af[1] = Ps[warp * 16 + g + 8][kc * 8 + tig    ];
            af[2] = Ps[warp * 16 + g    ][kc * 8 + tig + 4];
            af[3] = Ps[warp * 16 + g + 8][kc * 8 + tig + 4];
            uint32_t bf[8][2];
#pragma unroll
            for (int nt = 0; nt < 8; nt++) {
                bf[nt][0] = Vs[buf][kc * 8 + tig    ][nt * 8 + g];
                bf[nt][1] = Vs[buf][kc * 8 + tig + 4][nt * 8 + g];
            }
#pragma unroll
            for (int nt = 0; nt < 8; nt++)
                mma_tf32(o_acc[nt], af, bf[nt]);
        }
        __syncthreads();  // all reads of buf done before it is re-issued at kb+2
    }

    // ---- epilogue: normalize, store tf32 bits in [b][h][s][d] layout ----
    uint32_t* Op = g_att + base;
    const float inv0 = 1.0f / l_i[0];
    const float inv1 = 1.0f / l_i[1];
#pragma unroll
    for (int nt = 0; nt < 8; nt++) {
        const int d0 = nt * 8 + tig * 2;
        Op[(size_t)r_lo * DK_ + d0    ] = f2tf32(o_acc[nt][0] * inv0);
        Op[(size_t)r_lo * DK_ + d0 + 1] = f2tf32(o_acc[nt][1] * inv0);
        Op[(size_t)r_hi * DK_ + d0    ] = f2tf32(o_acc[nt][2] * inv1);
        Op[(size_t)r_hi * DK_ + d0 + 1] = f2tf32(o_acc[nt][3] * inv1);
    }
}

// ---------------------------------------------------------------------------
// Launch
// ---------------------------------------------------------------------------
extern "C" void kernel_launch(void* const* d_in, const int* in_sizes, int n_in,
                              void* d_out, int out_size) {
    (void)in_sizes; (void)n_in; (void)out_size;
    const float* query = (const float*)d_in[0];
    const float* key   = (const float*)d_in[1];
    const float* value = (const float*)d_in[2];
    const float* Wq = (const float*)d_in[4];
    const float* bq = (const float*)d_in[5];
    const float* Wk = (const float*)d_in[6];
    const float* bk = (const float*)d_in[7];
    const float* Wv = (const float*)d_in[8];
    const float* bv = (const float*)d_in[9];
    const float* Wo = (const float*)d_in[10];
    const float* bo = (const float*)d_in[11];
    float* out = (float*)d_out;

    cvt_weights<<<dim3(D_ * D_ / 1024, 4), 256>>>(Wq, Wk, Wv, Wo);

    dim3 gqkv(D_ / GBN, MTOT / GBM, 3);
    qkv_gemm<<<gqkv, 256>>>(query, key, value, bq, bk, bv);

    attn_tc<<<dim3(S_ / BQ, H_, B_), 128>>>();

    out_gemm<<<dim3(D_ / GBN, MTOT / GBM), 256>>>(bo, out);
}